// round 6
// baseline (speedup 1.0000x reference)
#include <cuda_runtime.h>
#include <cuda_bf16.h>
#include <cstdint>
#include <cstddef>

// y[32,11008] = x[32,4096] @ (Wq * scale)^T + bias
// Base-ISA (target sm_103): mma.sync m16n8k16 bf16 + cp.async 5-stage W ring.
// Ternary W -> bf16 via pure ALU bit tricks (no I2F). x -> hi/lo bf16 split.
// TM=64, grid=172 (all SMs), 8 warps = 4 M-warps x 2 N-groups.

#define OUTN 11008
#define INK  4096
#define TM   64
#define KC   64
#define NCHUNK (INK / KC)   // 64
#define NCTA (OUTN / TM)    // 172
#define NTHREADS 256
#define XROW 160            // x smem row stride (bytes)
#define WROW 272            // W smem row stride (bytes)
#define WSTAGE (TM * WROW)  // 17408
#define STAGES 5
#define XTILE (64 * XROW)   // 10240
#define SMEM_X0 (STAGES * WSTAGE)
#define SMEM_X1 (SMEM_X0 + XTILE)
#define SMEM_TOTAL (SMEM_X1 + XTILE)   // 107520

// ternary int32 pair -> packed bf16x2 {0,+-1.0}; 4 lat-4 ALU ops.
__device__ __forceinline__ uint32_t tern2bf(uint32_t w0, uint32_t w1) {
    uint32_t p = __byte_perm(w0, w1, 0x5410);   // [b0w0, b1w0, b0w1, b1w1]
    uint32_t m = (p & 0x00010001u) * 0x3F80u;   // magnitude per 16-bit half
    return m | (p & 0x80008000u);               // sign bit per half
}

__device__ __forceinline__ void mma16816(float d[4],
                                         uint32_t a0, uint32_t a1, uint32_t a2, uint32_t a3,
                                         uint32_t b0, uint32_t b1) {
    asm volatile(
        "mma.sync.aligned.m16n8k16.row.col.f32.bf16.bf16.f32 "
        "{%0,%1,%2,%3}, {%4,%5,%6,%7}, {%8,%9}, {%0,%1,%2,%3};\n"
        : "+f"(d[0]), "+f"(d[1]), "+f"(d[2]), "+f"(d[3])
        : "r"(a0), "r"(a1), "r"(a2), "r"(a3), "r"(b0), "r"(b1));
}

__device__ __forceinline__ void cp16(uint32_t dst, const void* src) {
    asm volatile("cp.async.cg.shared.global [%0], [%1], 16;\n" :: "r"(dst), "l"(src));
}
__device__ __forceinline__ void cp_commit() {
    asm volatile("cp.async.commit_group;\n" ::: "memory");
}
__device__ __forceinline__ void cp_wait3() {
    asm volatile("cp.async.wait_group 3;\n" ::: "memory");
}

struct XV { float4 a, b; };

__device__ __forceinline__ XV load_x(const float* __restrict__ X, int tid, int ch) {
    XV v;
    int f0 = tid, f1 = tid + NTHREADS;
    v.a = *reinterpret_cast<const float4*>(X + (size_t)(f0 >> 4) * INK + ch * KC + (f0 & 15) * 4);
    v.b = *reinterpret_cast<const float4*>(X + (size_t)(f1 >> 4) * INK + ch * KC + (f1 & 15) * 4);
    return v;
}

__device__ __forceinline__ void cvt_store_one(float4 u, int f, unsigned char* xb) {
    int b  = f >> 4;
    int k4 = (f & 15) * 4;
    __nv_bfloat16 h0 = __float2bfloat16_rn(u.x);
    __nv_bfloat16 h1 = __float2bfloat16_rn(u.y);
    __nv_bfloat16 h2 = __float2bfloat16_rn(u.z);
    __nv_bfloat16 h3 = __float2bfloat16_rn(u.w);
    __nv_bfloat16 l0 = __float2bfloat16_rn(u.x - __bfloat162float(h0));
    __nv_bfloat16 l1 = __float2bfloat16_rn(u.y - __bfloat162float(h1));
    __nv_bfloat16 l2 = __float2bfloat16_rn(u.z - __bfloat162float(h2));
    __nv_bfloat16 l3 = __float2bfloat16_rn(u.w - __bfloat162float(h3));
    __nv_bfloat162 hp0; hp0.x = h0; hp0.y = h1;
    __nv_bfloat162 hp1; hp1.x = h2; hp1.y = h3;
    __nv_bfloat162 lp0; lp0.x = l0; lp0.y = l1;
    __nv_bfloat162 lp1; lp1.x = l2; lp1.y = l3;
    uint2 hv = make_uint2(*reinterpret_cast<uint32_t*>(&hp0), *reinterpret_cast<uint32_t*>(&hp1));
    uint2 lv = make_uint2(*reinterpret_cast<uint32_t*>(&lp0), *reinterpret_cast<uint32_t*>(&lp1));
    *reinterpret_cast<uint2*>(xb + b * XROW + k4 * 2) = hv;
    *reinterpret_cast<uint2*>(xb + (b + 32) * XROW + k4 * 2) = lv;
}

__device__ __forceinline__ void store_x(XV v, unsigned char* xb, int tid) {
    cvt_store_one(v.a, tid, xb);
    cvt_store_one(v.b, tid + NTHREADS, xb);
}

// W cp.async: 64 rows x 256 B per chunk = 1024 x 16B / 256 threads = 4 each.
__device__ __forceinline__ void issue_w(const char* srcbase, uint32_t dstbase, int ch) {
#pragma unroll
    for (int j = 0; j < 4; ++j) {
        cp16(dstbase + j * (16 * WROW),
             srcbase + (size_t)j * 16 * INK * 4 + (size_t)ch * 256);
    }
}

// 4 M-warps (mwid) x 2 N-groups (ng). acc[0..1]=hi batches, acc[2..3]=lo.
__device__ __forceinline__ void compute(const unsigned char* wsm, const unsigned char* xb,
                                        int mwid, int ng, int lane, float acc[4][4]) {
    int rr = lane >> 2;
    int cc = lane & 3;
    const unsigned char* wr0 = wsm + (mwid * 16 + rr) * WROW + cc * 16;
    const unsigned char* xr  = xb + (ng * 16 + rr) * XROW + cc * 8;
#pragma unroll
    for (int s = 0; s < 4; ++s) {
        uint4 wa = *reinterpret_cast<const uint4*>(wr0 + s * 64);
        uint4 wb = *reinterpret_cast<const uint4*>(wr0 + 8 * WROW + s * 64);
        uint32_t a0 = tern2bf(wa.x, wa.y);
        uint32_t a2 = tern2bf(wa.z, wa.w);
        uint32_t a1 = tern2bf(wb.x, wb.y);
        uint32_t a3 = tern2bf(wb.z, wb.w);
#pragma unroll
        for (int i = 0; i < 2; ++i) {
            uint2 bh = *reinterpret_cast<const uint2*>(xr + i * (8 * XROW) + s * 32);
            uint2 bl = *reinterpret_cast<const uint2*>(xr + i * (8 * XROW) + 32 * XROW + s * 32);
            mma16816(acc[i],     a0, a1, a2, a3, bh.x, bh.y);
            mma16816(acc[i + 2], a0, a1, a2, a3, bl.x, bl.y);
        }
    }
}

__global__ void __launch_bounds__(NTHREADS)
lin2b_kernel(const float* __restrict__ X, const int* __restrict__ W,
             const float* __restrict__ SC, const float* __restrict__ BI,
             float* __restrict__ OUT)
{
    extern __shared__ __align__(16) unsigned char smem[];
    unsigned char* xsm[2] = { smem + SMEM_X0, smem + SMEM_X1 };

    int tid  = threadIdx.x;
    int wid  = tid >> 5;
    int lane = tid & 31;
    int mwid = wid & 3;
    int ng   = wid >> 2;
    int rr   = lane >> 2;
    int cc   = lane & 3;
    int row0 = blockIdx.x * TM;

    // cp.async thread mapping: rows tr, tr+16, tr+32, tr+48; 16B col c16
    int tr  = tid >> 4;          // 0..15
    int c16 = tid & 15;
    const char* wsrc = reinterpret_cast<const char*>(
        W + (size_t)(row0 + tr) * INK + c16 * 4);
    uint32_t smem_u = (uint32_t)__cvta_generic_to_shared(smem);
    uint32_t wdst_t = smem_u + tr * WROW + c16 * 16;

    float acc[4][4];
#pragma unroll
    for (int i = 0; i < 4; ++i)
#pragma unroll
        for (int j = 0; j < 4; ++j) acc[i][j] = 0.0f;

    // ---- prologue ----
#pragma unroll
    for (int p = 0; p < STAGES - 1; ++p) {
        issue_w(wsrc, wdst_t + p * WSTAGE, p);
        cp_commit();
    }
    {
        XV v = load_x(X, tid, 0);
        store_x(v, xsm[0], tid);
    }

    // ---- main loop ----
#pragma unroll 1
    for (int c = 0; c < NCHUNK; ++c) {
        XV v;
        bool morex = (c + 1) < NCHUNK;
        if (morex) v = load_x(X, tid, c + 1);

        cp_wait3();
        __syncthreads();

        int cn = c + STAGES - 1;
        if (cn < NCHUNK) issue_w(wsrc, wdst_t + (cn % STAGES) * WSTAGE, cn);
        cp_commit();

        compute(smem + (c % STAGES) * WSTAGE, xsm[c & 1], mwid, ng, lane, acc);
        if (morex) store_x(v, xsm[(c + 1) & 1], tid);
    }

    // ---- epilogue ----
    int o0 = row0 + mwid * 16 + rr;
    int o1 = o0 + 8;
    float s0 = SC[o0], bi0 = BI[o0];
    float s1 = SC[o1], bi1 = BI[o1];
#pragma unroll
    for (int i = 0; i < 2; ++i) {
        int b0 = (ng * 2 + i) * 8 + 2 * cc;
        int b1 = b0 + 1;
        float v00 = acc[i][0] + acc[i + 2][0];
        float v01 = acc[i][1] + acc[i + 2][1];
        float v10 = acc[i][2] + acc[i + 2][2];
        float v11 = acc[i][3] + acc[i + 2][3];
        OUT[(size_t)b0 * OUTN + o0] = fmaf(s0, v00, bi0);
        OUT[(size_t)b1 * OUTN + o0] = fmaf(s0, v01, bi0);
        OUT[(size_t)b0 * OUTN + o1] = fmaf(s1, v10, bi1);
        OUT[(size_t)b1 * OUTN + o1] = fmaf(s1, v11, bi1);
    }
}

extern "C" void kernel_launch(void* const* d_in, const int* in_sizes, int n_in,
                              void* d_out, int out_size) {
    (void)in_sizes; (void)n_in; (void)out_size;
    const float* x  = (const float*)d_in[0];
    const int*   wq = (const int*)d_in[1];
    const float* sc = (const float*)d_in[2];
    const float* bi = (const float*)d_in[3];
    float* out = (float*)d_out;

    cudaFuncSetAttribute(lin2b_kernel,
                         cudaFuncAttributeMaxDynamicSharedMemorySize, SMEM_TOTAL);
    lin2b_kernel<<<NCTA, NTHREADS, SMEM_TOTAL>>>(x, wq, sc, bi, out);
}